// round 17
// baseline (speedup 1.0000x reference)
#include <cuda_runtime.h>
#include <cstdint>

// x:      (2, 64, 32, 32, 32) fp32
// weight: (64, 32, 3, 3, 3)   fp32
// bias:   (32,)               fp32
// out:    (2, 32, 66, 66, 66) fp32
//
// Winograd F(2x2,3x3) in (h,w), direct sum over kd.
// This round: V double-buffered; V(cc+1) built by warps 4-7 WHILE warps 0-3
// run the multiply for chunk cc (warp-specialized phase overlap).

#define OUT_S 66
#define PLANE 4356
#define CH_STRIDE 287496
#define CIC 4
#define NCHUNK 16

// smem layout (bytes)
#define X_BYTES 3840                // 4ci * 4dd*10*6 * 4
#define SM_U0   (2 * X_BYTES)       // 7680
#define U_BYTES 27648               // 3kd * 4ci * 16pt * 36 * 4
#define SM_V    (SM_U0 + 2 * U_BYTES)   // 62976
#define V_BYTES 8704                // 16 rows * 136 words * 4
#define MSM_BYTES 16896             // 16pt*33co*8t*4  (< 2*V_BYTES = 17408)
#define SM_TOTAL (SM_V + 2 * V_BYTES)   // 80384

#define VCI 136

// Precomputed transformed weights: [kd][ci][pt][36] (co in [0,32), pad 4)
__device__ __align__(16) float g_U[3 * 64 * 16 * 36];

#define U_BLOCKS 24
#define DHROW_BLOCKS 2080
#define WPAIR_BLOCKS 1024
#define PREP_BLOCKS (U_BLOCKS + DHROW_BLOCKS + WPAIR_BLOCKS)

// ---------------------------------------------------------------------------
__global__ void prep_kernel(const float* __restrict__ w,
                            const float* __restrict__ bias,
                            float* __restrict__ out) {
    const int b   = blockIdx.x;
    const int tid = threadIdx.x;
    if (b < U_BLOCKS) {
        int i = b * 256 + tid;
        int kd = i >> 11;
        int r  = i & 2047;
        int ci = r >> 5;
        int co = r & 31;
        float g[3][3];
#pragma unroll
        for (int kh = 0; kh < 3; ++kh)
#pragma unroll
            for (int kw = 0; kw < 3; ++kw)
                g[kh][kw] = w[(ci * 32 + co) * 27
                              + (26 - (kd * 9 + kh * 3 + kw))];
        float tg[3][4];
#pragma unroll
        for (int kh = 0; kh < 3; ++kh) {
            tg[kh][0] = g[kh][0];
            tg[kh][1] = 0.5f * (g[kh][0] + g[kh][1] + g[kh][2]);
            tg[kh][2] = 0.5f * (g[kh][0] - g[kh][1] + g[kh][2]);
            tg[kh][3] = g[kh][2];
        }
        float* dst = g_U + ((kd * 64 + ci) * 16) * 36 + co;
#pragma unroll
        for (int q = 0; q < 4; ++q) {
            dst[(0 * 4 + q) * 36] = tg[0][q];
            dst[(1 * 4 + q) * 36] = 0.5f * (tg[0][q] + tg[1][q] + tg[2][q]);
            dst[(2 * 4 + q) * 36] = 0.5f * (tg[0][q] - tg[1][q] + tg[2][q]);
            dst[(3 * 4 + q) * 36] = tg[2][q];
        }
    } else if (b < U_BLOCKS + DHROW_BLOCKS) {
        int wg   = (b - U_BLOCKS) * 8 + (tid >> 5);
        int lane = tid & 31;
        int ch = wg / 260;
        int r  = wg - ch * 260;
        int d, h;
        if (r < 132) { d = 64 + (r >= 66 ? 1 : 0); h = r - (r >= 66 ? 66 : 0); }
        else         { int r2 = r - 132; d = r2 >> 1; h = 64 + (r2 & 1); }
        float bv = __ldg(&bias[ch & 31]);
        float* row = out + (size_t)ch * CH_STRIDE + (size_t)d * PLANE + h * OUT_S;
        for (int i = lane; i < OUT_S; i += 32) row[i] = bv;
    } else {
        int idx = (b - U_BLOCKS - DHROW_BLOCKS) * 256 + tid;
        int ch  = idx >> 12;
        int rem = idx & 4095;
        int d   = rem >> 6;
        int h   = rem & 63;
        float bv = __ldg(&bias[ch & 31]);
        float2* p = (float2*)(out + (size_t)ch * CH_STRIDE
                              + (size_t)d * PLANE + h * OUT_S + 64);
        *p = make_float2(bv, bv);
    }
}

// ---------------------------------------------------------------------------
__device__ __forceinline__ void cp4_zfill(uint32_t saddr, const float* g, int ok) {
    asm volatile("cp.async.ca.shared.global [%0], [%1], 4, %2;"
                 :: "r"(saddr), "l"(g), "r"(ok ? 4 : 0) : "memory");
}
__device__ __forceinline__ void cp16(uint32_t saddr, const float4* g) {
    asm volatile("cp.async.cg.shared.global [%0], [%1], 16;"
                 :: "r"(saddr), "l"(g) : "memory");
}
__device__ __forceinline__ void cp_commit() {
    asm volatile("cp.async.commit_group;" ::: "memory");
}
template <int N>
__device__ __forceinline__ void cp_wait() {
    asm volatile("cp.async.wait_group %0;" :: "n"(N) : "memory");
}

// ---------------------------------------------------------------------------
// Block = 256 threads. CTA tile: 2 zd x 8 h x 4 w (z coords) = 8 hw-tiles.
// Multiply decode: tp = tid&3, cog = (tid>>2)&3, pt = tid>>4.
// acc[zd 2][e 2][co-pair 4] f32x2.
// Per chunk: warps 0-3 issue cp(cc+1); all multiply ci{0,1}(V_cc);
// cp_wait+sync; warps 4-7 build V(cc+1) while warps 0-3 multiply ci{2,3};
// warps 4-7 then multiply ci{2,3}; sync.
// Grid (8,4,32) = 1024 CTAs; 2 co-resident per SM.
// ---------------------------------------------------------------------------
__global__ void __launch_bounds__(256, 2)
conv_wino_kernel(const float* __restrict__ x,
                 const float* __restrict__ bias,
                 float* __restrict__ out) {
    extern __shared__ __align__(16) char smem[];
    uint32_t sb;
    asm("{ .reg .u64 t; cvta.to.shared.u64 t, %1; cvt.u32.u64 %0, t; }"
        : "=r"(sb) : "l"(smem));

    const int tid = threadIdx.x;
    const int tp  = tid & 3;
    const int cog = (tid >> 2) & 3;
    const int pt  = tid >> 4;                 // 0..15

    const int tw = blockIdx.x;                // 0..7
    const int th = blockIdx.y;                // 0..3
    const int nz = blockIdx.z;                // 0..31
    const int n  = nz >> 4;
    const int td = nz & 15;
    const int zd0 = td * 2, zh0 = th * 8, zw0 = tw * 4;

    const float* xn = x + (size_t)n * (64 * 32768);

    // cp issue: warps 0-3 only (tid < 128)
    auto issue_chunk = [&](int cc, int buf) {
        uint32_t sx = sb + buf * X_BYTES;
#pragma unroll
        for (int j = 0; j < 8; ++j) {
            int i = tid + j * 128;
            if (i < 960) {
                int ci = i / 240;
                int r  = i - ci * 240;
                int dd = r / 60;
                int r2 = r - dd * 60;
                int hh = r2 / 6;
                int ww = r2 - hh * 6;
                int gd = zd0 - 1 + dd;
                int gh = zh0 - 1 + hh;
                int gw = zw0 - 1 + ww;
                int ok = (gd >= 0 && gd < 32 && gh >= 0 && gh < 32 &&
                          gw >= 0 && gw < 32);
                const float* g = xn + (((size_t)(cc * CIC + ci) * 32 + (gd & 31))
                                       * 32 + (gh & 31)) * 32 + (gw & 31);
                cp4_zfill(sx + i * 4, g, ok);
            }
        }
        uint32_t su = sb + SM_U0 + buf * U_BYTES;
#pragma unroll
        for (int j = 0; j < 14; ++j) {
            int i = tid + j * 128;
            if (i < 1728) {
                int kd = i / 576;
                int r  = i - kd * 576;
                const float4* src = (const float4*)
                    (g_U + (kd * 64 + cc * CIC) * (16 * 36)) + r;
                cp16(su + (kd * 576 + r) * 16, src);
            }
        }
        cp_commit();
    };

    // V build: warps 4-7 (tid >= 128), 128 units (dd 4, ci 4, tile 8)
    auto build_V = [&](int xbuf, int vbuf) {
        int u  = tid - 128;
        int t  = u & 7;
        int ci = (u >> 3) & 3;
        int dd = u >> 5;                      // 0..3
        int a  = t >> 1, b2 = t & 1;
        const float* dp = (const float*)(smem + xbuf * X_BYTES)
                        + ci * 240 + dd * 60 + (2 * a) * 6 + 2 * b2;
        float rt[4][4];
#pragma unroll
        for (int i = 0; i < 4; ++i) {
            float d0 = dp[i * 6 + 0], d1 = dp[i * 6 + 1];
            float d2 = dp[i * 6 + 2], d3 = dp[i * 6 + 3];
            rt[i][0] = d0 - d2;
            rt[i][1] = d1 + d2;
            rt[i][2] = d2 - d1;
            rt[i][3] = d1 - d3;
        }
        float* vd = (float*)(smem + SM_V + vbuf * V_BYTES)
                  + (dd * 4 + ci) * VCI + t;
#pragma unroll
        for (int q = 0; q < 4; ++q) {
            vd[(0 * 4 + q) * 8] = rt[0][q] - rt[2][q];
            vd[(1 * 4 + q) * 8] = rt[1][q] + rt[2][q];
            vd[(2 * 4 + q) * 8] = rt[2][q] - rt[1][q];
            vd[(3 * 4 + q) * 8] = rt[1][q] - rt[3][q];
        }
    };

    // acc[zd][e][j]
    unsigned long long acc[2][2][4];
#pragma unroll
    for (int a = 0; a < 2; ++a)
#pragma unroll
    for (int e = 0; e < 2; ++e)
#pragma unroll
    for (int j = 0; j < 4; ++j) acc[a][e][j] = 0ull;

    // multiply for ci in [c0, c1) on V buffer vbuf, U buffer ubuf
    auto multiply = [&](int c0, int c1, int vbuf, int ubuf) {
        const float* Vb = (const float*)(smem + SM_V + vbuf * V_BYTES);
        const float* Ub = (const float*)(smem + SM_U0 + ubuf * U_BYTES);
#pragma unroll
        for (int ci = c0; ci < c1; ++ci) {
            unsigned long long xv[4][2];
#pragma unroll
            for (int dd = 0; dd < 4; ++dd) {
                float2 f = *(const float2*)
                    (Vb + (dd * 4 + ci) * VCI + pt * 8 + 2 * tp);
                asm("mov.b64 %0, {%1, %1};" : "=l"(xv[dd][0]) : "f"(f.x));
                asm("mov.b64 %0, {%1, %1};" : "=l"(xv[dd][1]) : "f"(f.y));
            }
#pragma unroll
            for (int kd = 0; kd < 3; ++kd) {
                const float* up = Ub + ((kd * 4 + ci) * 16 + pt) * 36 + 8 * cog;
                ulonglong2 w0 = *(const ulonglong2*)up;
                ulonglong2 w1 = *(const ulonglong2*)(up + 4);
#pragma unroll
                for (int zd = 0; zd < 2; ++zd) {
#pragma unroll
                    for (int e = 0; e < 2; ++e) {
                        unsigned long long xvv = xv[zd + kd][e];
                        asm("fma.rn.f32x2 %0, %1, %2, %0;"
                            : "+l"(acc[zd][e][0]) : "l"(xvv), "l"(w0.x));
                        asm("fma.rn.f32x2 %0, %1, %2, %0;"
                            : "+l"(acc[zd][e][1]) : "l"(xvv), "l"(w0.y));
                        asm("fma.rn.f32x2 %0, %1, %2, %0;"
                            : "+l"(acc[zd][e][2]) : "l"(xvv), "l"(w1.x));
                        asm("fma.rn.f32x2 %0, %1, %2, %0;"
                            : "+l"(acc[zd][e][3]) : "l"(xvv), "l"(w1.y));
                    }
                }
            }
        }
    };

    // ---- prologue: load chunk 0, build V0 ----
    if (tid < 128) issue_chunk(0, 0);
    cp_wait<0>();
    __syncthreads();
    if (tid >= 128) build_V(0, 0);
    __syncthreads();

    // ---- pipelined main loop ----
#pragma unroll 1
    for (int cc = 0; cc < NCHUNK; ++cc) {
        const int buf = cc & 1;
        const bool more = (cc + 1 < NCHUNK);
        if (more && tid < 128) issue_chunk(cc + 1, buf ^ 1);
        multiply(0, 2, buf, buf);       // overlaps cp transfer
        if (more) {
            cp_wait<0>();
            __syncthreads();            // x(cc+1)/U(cc+1) visible to all
            if (tid >= 128) build_V(buf ^ 1, buf ^ 1);   // V(cc+1)
        }
        multiply(2, 4, buf, buf);       // warps 0-3 run this during build_V
        __syncthreads();                // V(cc+1) ready; V_cc reads done
    }

    // ---- output: per zd: stage M, transform Y = A^T M A, store cubes ----
    float* Msm = (float*)(smem + SM_V);    // [pt][33 co][8 t]
    const int t2  = tid & 7;
    const int co2 = (tid >> 3) & 31;
    const float bvv = __ldg(&bias[co2]);
    const int a2 = t2 >> 1, b2 = t2 & 1;

#pragma unroll 1
    for (int zd = 0; zd < 2; ++zd) {
#pragma unroll
        for (int e = 0; e < 2; ++e) {
#pragma unroll
            for (int j = 0; j < 4; ++j) {
                float2 v;
                asm("mov.b64 {%0, %1}, %2;"
                    : "=f"(v.x), "=f"(v.y) : "l"(acc[zd][e][j]));
                int co = 8 * cog + 2 * j;
                int t  = 2 * tp + e;
                Msm[(pt * 33 + co)     * 8 + t] = v.x;
                Msm[(pt * 33 + co + 1) * 8 + t] = v.y;
            }
        }
        __syncthreads();

        float m[16];
#pragma unroll
        for (int p = 0; p < 16; ++p)
            m[p] = Msm[(p * 33 + co2) * 8 + t2];
        float tq0[4], tq1[4];
#pragma unroll
        for (int p = 0; p < 4; ++p) {
            tq0[p] = m[4 * p] + m[4 * p + 1] + m[4 * p + 2];
            tq1[p] = m[4 * p + 1] - m[4 * p + 2] - m[4 * p + 3];
        }
        float Y[2][2];
        Y[0][0] = tq0[0] + tq0[1] + tq0[2];
        Y[0][1] = tq1[0] + tq1[1] + tq1[2];
        Y[1][0] = tq0[1] - tq0[2] - tq0[3];
        Y[1][1] = tq1[1] - tq1[2] - tq1[3];

        const int zg = zd0 + zd;
#pragma unroll
        for (int i = 0; i < 2; ++i) {
#pragma unroll
            for (int j = 0; j < 2; ++j) {
                const int hg = zh0 + 2 * a2 + i;
                const int wg = zw0 + 2 * b2 + j;
                float* base = out + (size_t)(n * 32 + co2) * CH_STRIDE
                            + (size_t)(2 * zg) * PLANE
                            + (2 * hg) * OUT_S + 2 * wg;
                float2 bb = make_float2(bvv, bvv);
                float2 bc = make_float2(bvv, Y[i][j] + bvv);
                *(float2*)(base)                 = bb;
                *(float2*)(base + OUT_S)         = bb;
                *(float2*)(base + PLANE)         = bb;
                *(float2*)(base + PLANE + OUT_S) = bc;
            }
        }
        __syncthreads();
    }
}

// ---------------------------------------------------------------------------
extern "C" void kernel_launch(void* const* d_in, const int* in_sizes, int n_in,
                              void* d_out, int out_size) {
    const float* x = nullptr;
    const float* w = nullptr;
    const float* b = nullptr;
    for (int i = 0; i < n_in; ++i) {
        if (in_sizes[i] == 4194304)    x = (const float*)d_in[i];
        else if (in_sizes[i] == 55296) w = (const float*)d_in[i];
        else if (in_sizes[i] == 32)    b = (const float*)d_in[i];
    }
    float* out = (float*)d_out;

    cudaFuncSetAttribute(conv_wino_kernel,
                         cudaFuncAttributeMaxDynamicSharedMemorySize, SM_TOTAL);

    prep_kernel<<<PREP_BLOCKS, 256>>>(w, b, out);

    dim3 grid(8, 4, 32);   // 1024 CTAs, 2 co-resident per SM
    conv_wino_kernel<<<grid, 256, SM_TOTAL>>>(x, b, out);
}